// round 7
// baseline (speedup 1.0000x reference)
#include <cuda_runtime.h>
#include <cuda_fp16.h>
#include <cstdint>

// Problem: B=128, L_IM=50, L_S=40, D=1024
// im = im_set[:,1:,:]  -> il = im_len-1 valid rows (9..49), stored padded to 64
// s  = s_seq[:,1:-2,:] -> sl = s_len-3  valid rows (7..37), stored padded to 40
// Rows >= valid length are never read (cp.async zfill), MMA fragments fully in
// the invalid region are skipped: accumulators stay 0 = reference's masked 0.
#define NBATCH 128
#define DDIM   1024
#define AROWS  64
#define SROWS  40

__device__ __align__(1024) __half g_A[(size_t)NBATCH * AROWS * DDIM];  // 16 MB
__device__ __align__(1024) __half g_S[(size_t)NBATCH * SROWS * DDIM];  // 10 MB

// ---------------- helpers ----------------
__device__ __forceinline__ uint32_t smem_u32(const void* p) {
    uint32_t a;
    asm("{ .reg .u64 t; cvta.to.shared.u64 t, %1; cvt.u32.u64 %0, t; }" : "=r"(a) : "l"(p));
    return a;
}

// cp.async with runtime src-size: 16 = real load, 0 = zero-fill (no L2 read)
#define CP_ASYNC16Z(dst, src, sz) \
    asm volatile("cp.async.cg.shared.global [%0], [%1], 16, %2;" \
                 :: "r"(dst), "l"(src), "r"(sz))
#define CP_COMMIT() asm volatile("cp.async.commit_group;" ::: "memory")
#define CP_WAIT1()  asm volatile("cp.async.wait_group 1;" ::: "memory")
#define CP_WAIT0()  asm volatile("cp.async.wait_group 0;" ::: "memory")

#define LDSM4(r, addr) \
    asm volatile("ldmatrix.sync.aligned.m8n8.x4.shared.b16 {%0,%1,%2,%3}, [%4];" \
                 : "=r"((r)[0]), "=r"((r)[1]), "=r"((r)[2]), "=r"((r)[3]) : "r"(addr))

#define MMA16816(c, a, b0, b1) \
    asm volatile("mma.sync.aligned.m16n8k16.row.col.f32.f16.f16.f32 " \
                 "{%0,%1,%2,%3},{%4,%5,%6,%7},{%8,%9},{%0,%1,%2,%3};" \
                 : "+f"((c)[0]), "+f"((c)[1]), "+f"((c)[2]), "+f"((c)[3]) \
                 : "r"((a)[0]), "r"((a)[1]), "r"((a)[2]), "r"((a)[3]), "r"(b0), "r"(b1))

__device__ __forceinline__ float wsum(float v) {
#pragma unroll
    for (int m = 16; m > 0; m >>= 1) v += __shfl_xor_sync(0xffffffffu, v, m);
    return v;
}

// ------------- conversion: fp32 -> fp16, valid rows only -------------
__global__ void convA_kernel(const float* __restrict__ im, const int* __restrict__ im_len) {
    int u = blockIdx.x * blockDim.x + threadIdx.x;        // < 128*64*128
    int i  = u >> 13;
    int r  = (u >> 7) & 63;
    int d0 = (u & 127) << 3;
    int L = im_len[i] - 1;
    if (r >= L || r >= 49) return;                        // rows never read (zfill)
    const float* src = im + ((size_t)i * 50 + r + 1) * DDIM + d0;
    float4 f0 = ((const float4*)src)[0];
    float4 f1 = ((const float4*)src)[1];
    union { uint4 v; __half2 h[4]; } pk;
    pk.h[0] = __float22half2_rn(make_float2(f0.x, f0.y));
    pk.h[1] = __float22half2_rn(make_float2(f0.z, f0.w));
    pk.h[2] = __float22half2_rn(make_float2(f1.x, f1.y));
    pk.h[3] = __float22half2_rn(make_float2(f1.z, f1.w));
    *((uint4*)(g_A + ((size_t)i * AROWS + r) * DDIM + d0)) = pk.v;
}

__global__ void convS_kernel(const float* __restrict__ s, const int* __restrict__ s_len) {
    int u = blockIdx.x * blockDim.x + threadIdx.x;        // < 128*40*128
    int i   = u / (SROWS * 128);
    int rem = u - i * (SROWS * 128);
    int r  = rem >> 7;
    int d0 = (rem & 127) << 3;
    int L = s_len[i] - 3;
    if (r >= L || r >= 37) return;
    const float* src = s + ((size_t)i * 40 + r + 1) * DDIM + d0;
    float4 f0 = ((const float4*)src)[0];
    float4 f1 = ((const float4*)src)[1];
    union { uint4 v; __half2 h[4]; } pk;
    pk.h[0] = __float22half2_rn(make_float2(f0.x, f0.y));
    pk.h[1] = __float22half2_rn(make_float2(f0.z, f0.w));
    pk.h[2] = __float22half2_rn(make_float2(f1.x, f1.y));
    pk.h[3] = __float22half2_rn(make_float2(f1.z, f1.w));
    *((uint4*)(g_S + ((size_t)i * SROWS + r) * DDIM + d0)) = pk.v;
}

// ------------- GEMM + fused masked max/sum epilogue -------------
// CTA: 512 threads, tile M=128 (2 i), N=320 (8 j x 40), K=1024 in 16 chunks of 64.
// Warp grid 8(m) x 2(n): warp tile 16 x 160; wn = wid&1 -> SMSP spread keeps
// m-fragment trimming balanced across schedulers.
#define PITCH     144
#define ASTAGE    18432              // 128*144
#define STAGE_SZ  64512              // ASTAGE + 320*144
#define SMEM_BYTES (128 + STAGE_SZ * 3)
#define CPITCH    326                // even -> float2-aligned; 326*4 % 128 = 24

__global__ void __launch_bounds__(512, 1) align_gemm_kernel(
        const int* __restrict__ im_len, const int* __restrict__ s_len,
        float* __restrict__ out) {
    extern __shared__ __align__(16) char smem[];
    const int tid  = threadIdx.x;
    const int lane = tid & 31;
    const int wid  = tid >> 5;
    const int wn   = wid & 1;        // N offset wn*160
    const int wm   = wid >> 1;       // M fragment wm*16 (0..7)
    const int jb = blockIdx.x;       // 0..15
    const int ib = blockIdx.y;       // 0..63
    const uint32_t sbase = smem_u32(smem) + 128;   // stages start at +128

    // ---- lengths & compute masks ----
    const int il0 = __ldg(&im_len[ib * 2 + 0]) - 1;
    const int il1 = __ldg(&im_len[ib * 2 + 1]) - 1;
    int sl[8];
#pragma unroll
    for (int j = 0; j < 8; j++) sl[j] = __ldg(&s_len[jb * 8 + j]) - 3;

    const int il_w = (wm < 4) ? il0 : il1;
    const bool mt_active = ((wm & 3) * 16) < il_w;
    uint32_t nt_mask = 0;
#pragma unroll
    for (int nt = 0; nt < 20; nt++) {
        int j = wn * 4 + nt / 5;
        int w = (nt % 5) * 8;
        if (w < sl[j]) nt_mask |= (1u << nt);
    }

    // ---- per-thread load setup (addresses fixed, advance by 128B per kt) ----
    // A: 2 chunks/thread. idx = tid + q*512; row = idx>>3 (0..127); c = idx&7.
    const char* srcA[2]; uint32_t dstA[2], szA[2];
#pragma unroll
    for (int q = 0; q < 2; q++) {
        int idx = tid + q * 512, row = idx >> 3, c = idx & 7;
        int r = row & 63;
        szA[q] = (r < ((row >> 6) ? il1 : il0)) ? 16u : 0u;
        srcA[q] = (const char*)(g_A + ((size_t)(ib * 128 + row)) * DDIM) + c * 16;
        dstA[q] = sbase + row * PITCH + c * 16;
    }
    // B: 5 chunks/thread. row in 0..319; j = row/40, w = row%40.
    const char* srcB[5]; uint32_t dstB[5], szB[5];
#pragma unroll
    for (int q = 0; q < 5; q++) {
        int idx = tid + q * 512, row = idx >> 3, c = idx & 7;
        int j = (row * 205) >> 13;           // row/40 for row<320
        int w = row - j * 40;
        szB[q] = (w < sl[j]) ? 16u : 0u;
        srcB[q] = (const char*)(g_S + ((size_t)(jb * 320 + row)) * DDIM) + c * 16;
        dstB[q] = sbase + ASTAGE + row * PITCH + c * 16;
    }

    // ldmatrix lane addresses
    const int quad = lane >> 3, r8 = lane & 7;
    const uint32_t a_lane = (uint32_t)((wm * 16 + (quad & 1) * 8 + r8) * PITCH
                                       + (quad >> 1) * 16);
    const uint32_t b_base = (uint32_t)(ASTAGE
                                       + (wn * 160 + (quad >> 1) * 8 + r8) * PITCH
                                       + (quad & 1) * 16);

    float c[20][4];
#pragma unroll
    for (int nt = 0; nt < 20; nt++)
#pragma unroll
        for (int q = 0; q < 4; q++) c[nt][q] = 0.0f;

    // ---- prologue: 2 stages in flight ----
#pragma unroll
    for (int p = 0; p < 2; p++) {
        uint32_t so = (uint32_t)(p * STAGE_SZ), ko = (uint32_t)(p * 128);
#pragma unroll
        for (int q = 0; q < 2; q++) CP_ASYNC16Z(dstA[q] + so, srcA[q] + ko, szA[q]);
#pragma unroll
        for (int q = 0; q < 5; q++) CP_ASYNC16Z(dstB[q] + so, srcB[q] + ko, szB[q]);
        CP_COMMIT();
    }

    int stg_load = 2;   // stage receiving kt+2
#pragma unroll 1
    for (int kt = 0; kt < 16; kt++) {
        if (kt < 15) { CP_WAIT1(); } else { CP_WAIT0(); }
        __syncthreads();
        if (kt + 2 < 16) {
            uint32_t so = (uint32_t)(stg_load * STAGE_SZ), ko = (uint32_t)((kt + 2) * 128);
#pragma unroll
            for (int q = 0; q < 2; q++) CP_ASYNC16Z(dstA[q] + so, srcA[q] + ko, szA[q]);
#pragma unroll
            for (int q = 0; q < 5; q++) CP_ASYNC16Z(dstB[q] + so, srcB[q] + ko, szB[q]);
            CP_COMMIT();
            stg_load = (stg_load + 1 == 3) ? 0 : stg_load + 1;
        }

        const int stg = kt % 3;
        const uint32_t stga = sbase + stg * STAGE_SZ;
        if (mt_active) {
#pragma unroll
            for (int step = 0; step < 4; step++) {
                uint32_t a[4];
                LDSM4(a, stga + a_lane + step * 32);
#pragma unroll
                for (int bc = 0; bc < 10; bc++) {
                    if ((nt_mask >> (2 * bc)) & 3) {
                        uint32_t b[4];
                        LDSM4(b, stga + b_base + bc * 16 * PITCH + step * 32);
                        if ((nt_mask >> (2 * bc)) & 1)
                            MMA16816(c[2 * bc],     a, b[0], b[1]);
                        if ((nt_mask >> (2 * bc + 1)) & 1)
                            MMA16816(c[2 * bc + 1], a, b[2], b[3]);
                    }
                }
            }
        }
    }
    __syncthreads();       // compute done; smem reused for C

    // ---- store C tile to smem: [128][CPITCH] floats ----
    float* C   = (float*)smem;
    float* acc = (float*)(smem + 128 * CPITCH * 4);   // 16 floats (2 i x 8 j)
    float* red = acc + 16;                            // 2*320 floats
    if (tid < 16) acc[tid] = 0.0f;
    {
        int row = wm * 16 + (lane >> 2);
        int colb = wn * 160 + (lane & 3) * 2;
#pragma unroll
        for (int nt = 0; nt < 20; nt++) {
            int col = colb + nt * 8;
            *(float2*)&C[row * CPITCH + col]       = make_float2(c[nt][0], c[nt][1]);
            *(float2*)&C[(row + 8) * CPITCH + col] = make_float2(c[nt][2], c[nt][3]);
        }
    }
    __syncthreads();

    // ---- row part: row r (<49 per il), max over w<37 per j-block, summed over r ----
    {
        int row = tid & 127;
        int jpair = tid >> 7;              // 2 j-blocks per thread
        int il = row >> 6, ro = row & 63;
        const float* Cr = &C[row * CPITCH];
#pragma unroll
        for (int jj = 0; jj < 2; jj++) {
            int jblock = jpair * 2 + jj;
            float rm = Cr[jblock * 40];
#pragma unroll
            for (int w = 1; w < 37; w++) rm = fmaxf(rm, Cr[jblock * 40 + w]);
            float rs = wsum((ro < 49) ? rm : 0.0f);
            if (lane == 0) atomicAdd(&acc[il * 8 + jblock], rs);
        }
    }
    // ---- col part: col w (<37 per j-block), max over r<49 ----
    if (tid < 320) {
        int w = tid % 40;
#pragma unroll
        for (int il = 0; il < 2; il++) {
            const float* Cc = &C[il * 64 * CPITCH + tid];
            float cm = Cc[0];
#pragma unroll
            for (int r = 1; r < 49; r++) cm = fmaxf(cm, Cc[r * CPITCH]);
            red[il * 320 + tid] = (w < 37) ? cm : 0.0f;
        }
    }
    __syncthreads();
    if (tid < 16) {
        int il = tid >> 3, jj = tid & 7;
        float sum = acc[tid];
        const float* rp = &red[il * 320 + jj * 40];
#pragma unroll
        for (int w = 0; w < 37; w++) sum += rp[w];
        out[(ib * 2 + il) * NBATCH + jb * 8 + jj] = sum;
    }
}

extern "C" void kernel_launch(void* const* d_in, const int* in_sizes, int n_in,
                              void* d_out, int out_size) {
    (void)in_sizes; (void)n_in; (void)out_size;
    const float* im   = (const float*)d_in[0];
    const float* s    = (const float*)d_in[1];
    const int* im_len = (const int*)d_in[2];
    const int* s_len  = (const int*)d_in[3];
    float* out = (float*)d_out;

    convA_kernel<<<4096, 256>>>(im, im_len);
    convS_kernel<<<2560, 256>>>(s, s_len);

    cudaFuncSetAttribute(align_gemm_kernel,
                         cudaFuncAttributeMaxDynamicSharedMemorySize, SMEM_BYTES);
    dim3 grid(16, 64);
    align_gemm_kernel<<<grid, 512, SMEM_BYTES>>>(im_len, s_len, out);
}